// round 1
// baseline (speedup 1.0000x reference)
#include <cuda_runtime.h>
#include <math.h>

#define NT   256      // threads per block
#define NS   4096     // sequence length S
#define HALF 2048
// smem: z0(32KB) + z1(32KB) + scratch(32KB) + twiddle(16KB) = 114688 B
#define SMEM_BYTES (3*NS*8 + HALF*8)

__device__ __forceinline__ float2 cmulf(float2 a, float2 b){
    return make_float2(a.x*b.x - a.y*b.y, a.x*b.y + a.y*b.x);
}

// Stockham radix-2 DIT, N=4096, 12 stages, ping-pong src<->buf.
// Even stage count => result ends up back in src0. Caller must __syncthreads() before.
__device__ void do_fft(float2* src0, float2* buf, const float2* __restrict__ tw, int tid){
    float2* src = src0;
    float2* dst = buf;
    for (int s = 0; s < 12; s++){
        int Nss = 1 << s;
        #pragma unroll
        for (int it = 0; it < HALF/NT; it++){
            int j = tid + it*NT;
            int m = j & (Nss - 1);
            float2 a = src[j];
            float2 b = src[j + HALF];
            float2 w = tw[m << (11 - s)];      // exp(-2*pi*i * m / (2*Nss))
            float2 wb = cmulf(b, w);
            int base = ((j >> s) << (s + 1)) | m;
            dst[base]       = make_float2(a.x + wb.x, a.y + wb.y);
            dst[base + Nss] = make_float2(a.x - wb.x, a.y - wb.y);
        }
        __syncthreads();
        float2* t = src; src = dst; dst = t;
    }
}

__global__ void __launch_bounds__(NT, 2)
rmix_kernel(const float* __restrict__ x,
            const float* __restrict__ Ur, const float* __restrict__ Ui,
            const float* __restrict__ Vr, const float* __restrict__ Vi,
            const float* __restrict__ Wr, const float* __restrict__ Wi,
            const float* __restrict__ P1w, const float* __restrict__ P1b,
            const float* __restrict__ P2w, const float* __restrict__ P2b,
            const float* __restrict__ alphaP,
            float* __restrict__ out)
{
    extern __shared__ float2 sm[];
    float2* z0  = sm;            // 4096 complex
    float2* z1  = sm + NS;       // 4096 complex
    float2* scr = sm + 2*NS;     // 4096 complex ping-pong scratch
    float2* tw  = sm + 3*NS;     // 2048 twiddles
    // aliases into scr (free between FFT phases):
    float*  dbuf = (float*)scr;               // 4096 floats: delta table
    float*  red  = (float*)scr + NS;          // 512 floats: cross-warp reduce
    float*  hidf = (float*)scr + NS + 512;    // 16 floats: hidden[2][8]
    float*  pqf  = (float*)scr + NS + 512 + 16; // 64 floats: p,q[2][8] complex

    const int tid = threadIdx.x;
    const size_t row0 = (size_t)blockIdx.x * 2;

    // Twiddle table: tw[m] = exp(-i*pi*m/2048)
    for (int m = tid; m < HALF; m += NT){
        float sn, cs;
        sincospif(-(float)m * (1.0f/2048.0f), &sn, &cs);
        tw[m] = make_float2(cs, sn);
    }
    // Load the two input rows
    for (int k = tid; k < NS; k += NT){
        z0[k] = make_float2(x[row0*NS + k], 0.0f);
        z1[k] = make_float2(x[(row0+1)*NS + k], 0.0f);
    }
    __syncthreads();
    do_fft(z0, scr, tw, tid);
    do_fft(z1, scr, tw, tid);

    // ---- hidden = relu([Re z, Im z] @ P1w.T + P1b), both rows jointly ----
    float h[16];
    #pragma unroll
    for (int i = 0; i < 16; i++) h[i] = 0.0f;
    for (int k = tid; k < NS; k += NT){
        float2 a = z0[k], b = z1[k];
        #pragma unroll
        for (int r = 0; r < 8; r++){
            float wr_ = P1w[r*2*NS + k];
            float wi_ = P1w[r*2*NS + NS + k];
            h[r]   += a.x*wr_ + a.y*wi_;
            h[8+r] += b.x*wr_ + b.y*wi_;
        }
    }
    {
        #pragma unroll
        for (int i = 0; i < 16; i++){
            float v = h[i];
            #pragma unroll
            for (int o = 16; o > 0; o >>= 1) v += __shfl_down_sync(0xffffffffu, v, o);
            h[i] = v;
        }
        int warp = tid >> 5, lane = tid & 31;
        if (lane == 0){
            #pragma unroll
            for (int i = 0; i < 16; i++) red[warp*16 + i] = h[i];
        }
        __syncthreads();
        if (tid < 16){
            float s = 0.0f;
            #pragma unroll
            for (int w = 0; w < NT/32; w++) s += red[w*16 + tid];
            hidf[tid] = fmaxf(s + P1b[tid & 7], 0.0f);
        }
        __syncthreads();
    }

    const float alpha = *alphaP;

    // ---- per-row: delta table, then gain-scale z ----
    for (int rv = 0; rv < 2; rv++){
        float2* zz = rv ? z1 : z0;
        float hr[8];
        #pragma unroll
        for (int r = 0; r < 8; r++) hr[r] = hidf[rv*8 + r];
        for (int j = tid; j < NS; j += NT){
            const float* p2 = P2w + (size_t)j*8;
            float d = P2b[j];
            #pragma unroll
            for (int r = 0; r < 8; r++) d += hr[r]*p2[r];
            dbuf[j] = d;
        }
        __syncthreads();
        for (int k = tid; k < NS; k += NT){
            int   m2 = min(k, NS - k);
            float nf = (float)m2 * (1.0f/2048.0f);        // == |fftfreq|*2, exact
            float t  = nf / 0.2f;
            float lb = expf(-0.5f * t * t);
            float hd = 0.5f / (1.0f + expf(-((nf - 0.6f) / 0.1f)));
            float bg = fmaxf(1.0f + lb - hd, 0.0f);
            float scaled = nf * 4095.0f;
            float fl = floorf(scaled);
            int lo = (int)fl;
            int up = (int)ceilf(scaled);
            float frac = scaled - fl;
            float dlo = dbuf[lo];
            float dhi = dbuf[up];
            float g = fmaxf(bg + alpha * (dlo + (dhi - dlo)*frac), 0.0f);
            float2 v = zz[k];
            zz[k] = make_float2(v.x*g, v.y*g);
        }
        __syncthreads();
    }

    // ---- p = z@(Ur+iUi).T, q = z@(Vr+iVi).T, both rows jointly ----
    float acc[64];
    #pragma unroll
    for (int i = 0; i < 64; i++) acc[i] = 0.0f;
    for (int k = tid; k < NS; k += NT){
        float2 a = z0[k], b = z1[k];
        #pragma unroll
        for (int r = 0; r < 8; r++){
            float ur = Ur[r*NS + k], ui = Ui[r*NS + k];
            float vr = Vr[r*NS + k], vi = Vi[r*NS + k];
            acc[r*2]      += a.x*ur - a.y*ui;   // p row0
            acc[r*2+1]    += a.x*ui + a.y*ur;
            acc[16+r*2]   += a.x*vr - a.y*vi;   // q row0
            acc[16+r*2+1] += a.x*vi + a.y*vr;
            acc[32+r*2]   += b.x*ur - b.y*ui;   // p row1
            acc[32+r*2+1] += b.x*ui + b.y*ur;
            acc[48+r*2]   += b.x*vr - b.y*vi;   // q row1
            acc[48+r*2+1] += b.x*vi + b.y*vr;
        }
    }
    #pragma unroll
    for (int i = 0; i < 64; i++){
        float v = acc[i];
        #pragma unroll
        for (int o = 16; o > 0; o >>= 1) v += __shfl_down_sync(0xffffffffu, v, o);
        acc[i] = v;
    }
    {
        int warp = tid >> 5, lane = tid & 31;
        if (lane == 0){
            #pragma unroll
            for (int i = 0; i < 64; i++) red[warp*64 + i] = acc[i];
        }
        __syncthreads();
        if (tid < 64){
            float s2 = 0.0f;
            #pragma unroll
            for (int w = 0; w < NT/32; w++) s2 += red[w*64 + tid];
            pqf[tid] = s2;
        }
        __syncthreads();
    }

    // ---- gamma = p * conj(q); z += gamma @ (Wr+iWi).T; conj for inverse ----
    float g0r[8], g0i[8], g1r[8], g1i[8];
    #pragma unroll
    for (int r = 0; r < 8; r++){
        float pr = pqf[r*2],    pi = pqf[r*2+1];
        float qr = pqf[16+r*2], qi = pqf[16+r*2+1];
        g0r[r] = pr*qr + pi*qi;
        g0i[r] = pi*qr - pr*qi;
        pr = pqf[32+r*2]; pi = pqf[32+r*2+1];
        qr = pqf[48+r*2]; qi = pqf[48+r*2+1];
        g1r[r] = pr*qr + pi*qi;
        g1i[r] = pi*qr - pr*qi;
    }
    for (int k = tid; k < NS; k += NT){
        const float* wrp = Wr + (size_t)k*8;
        const float* wip = Wi + (size_t)k*8;
        float2 v0 = z0[k], v1 = z1[k];
        #pragma unroll
        for (int r = 0; r < 8; r++){
            float wr_ = wrp[r], wi_ = wip[r];
            v0.x += g0r[r]*wr_ - g0i[r]*wi_;
            v0.y += g0r[r]*wi_ + g0i[r]*wr_;
            v1.x += g1r[r]*wr_ - g1i[r]*wi_;
            v1.y += g1r[r]*wi_ + g1i[r]*wr_;
        }
        // conjugate: Re(ifft(z)) = Re(fft(conj(z)))/N
        z0[k] = make_float2(v0.x, -v0.y);
        z1[k] = make_float2(v1.x, -v1.y);
    }
    __syncthreads();
    do_fft(z0, scr, tw, tid);
    do_fft(z1, scr, tw, tid);

    const float invn = 1.0f/4096.0f;
    for (int n = tid; n < NS; n += NT){
        out[row0*NS + n]     = z0[n].x * invn;
        out[(row0+1)*NS + n] = z1[n].x * invn;
    }
}

extern "C" void kernel_launch(void* const* d_in, const int* in_sizes, int n_in,
                              void* d_out, int out_size)
{
    const float* x    = (const float*)d_in[0];
    const float* Ur   = (const float*)d_in[1];
    const float* Ui   = (const float*)d_in[2];
    const float* Vr   = (const float*)d_in[3];
    const float* Vi   = (const float*)d_in[4];
    const float* Wr   = (const float*)d_in[5];
    const float* Wi   = (const float*)d_in[6];
    const float* P1w  = (const float*)d_in[7];
    const float* P1b  = (const float*)d_in[8];
    const float* P2w  = (const float*)d_in[9];
    const float* P2b  = (const float*)d_in[10];
    const float* alph = (const float*)d_in[11];
    float* out = (float*)d_out;

    cudaFuncSetAttribute(rmix_kernel, cudaFuncAttributeMaxDynamicSharedMemorySize, SMEM_BYTES);
    rmix_kernel<<<1024, NT, SMEM_BYTES>>>(x, Ur, Ui, Vr, Vi, Wr, Wi,
                                          P1w, P1b, P2w, P2b, alph, out);
}

// round 2
// speedup vs baseline: 2.0545x; 2.0545x over previous
#include <cuda_runtime.h>
#include <math.h>

#define NT   256
#define NS   4096
#define PIDX(i) ((i) + ((i)>>4))
// float2: A(4352) + E(4352) + tw(256) = 8960 *8 = 71680
// float:  dbuf(4096) + red(512) + hidf(16) + pqf(64) = 4688 *4 = 18752
#define SMEM_BYTES 90432

__device__ __forceinline__ float2 cmul(float2 a, float2 b){
    return make_float2(fmaf(a.x,b.x,-a.y*b.y), fmaf(a.x,b.y,a.y*b.x));
}
__device__ __forceinline__ float2 cadd(float2 a,float2 b){return make_float2(a.x+b.x,a.y+b.y);}
__device__ __forceinline__ float2 csub(float2 a,float2 b){return make_float2(a.x-b.x,a.y-b.y);}

// 16-point DFT in registers (DIT 4x4). X[k] = sum_i x[i] w16^{ik}, w16=exp(-2pi i/16)
__device__ __forceinline__ void dft16(float2* a){
    float2 y[16];
    #pragma unroll
    for (int b=0;b<4;b++){
        float2 x0=a[b], x1=a[4+b], x2=a[8+b], x3=a[12+b];
        float2 t0=cadd(x0,x2), t1=csub(x0,x2), t2=cadd(x1,x3), t3=csub(x1,x3);
        y[b*4+0]=cadd(t0,t2);
        y[b*4+2]=csub(t0,t2);
        y[b*4+1]=make_float2(t1.x+t3.y, t1.y-t3.x);   // t1 - i*t3
        y[b*4+3]=make_float2(t1.x-t3.y, t1.y+t3.x);   // t1 + i*t3
    }
    const float C1=0.92387953251128674f, S1=0.38268343236508978f;
    const float C2=0.70710678118654752f;
    y[5]  = cmul(y[5],  make_float2( C1,-S1));   // w^1
    y[6]  = cmul(y[6],  make_float2( C2,-C2));   // w^2
    y[7]  = cmul(y[7],  make_float2( S1,-C1));   // w^3
    y[9]  = cmul(y[9],  make_float2( C2,-C2));   // w^2
    y[10] = make_float2(y[10].y, -y[10].x);      // w^4 = -i
    y[11] = cmul(y[11], make_float2(-C2,-C2));   // w^6
    y[13] = cmul(y[13], make_float2( S1,-C1));   // w^3
    y[14] = cmul(y[14], make_float2(-C2,-C2));   // w^6
    y[15] = cmul(y[15], make_float2(-C1, S1));   // w^9
    #pragma unroll
    for (int k1=0;k1<4;k1++){
        float2 x0=y[k1], x1=y[4+k1], x2=y[8+k1], x3=y[12+k1];
        float2 t0=cadd(x0,x2), t1=csub(x0,x2), t2=cadd(x1,x3), t3=csub(x1,x3);
        a[k1+0]  = cadd(t0,t2);
        a[k1+8]  = csub(t0,t2);
        a[k1+4]  = make_float2(t1.x+t3.y, t1.y-t3.x);
        a[k1+12] = make_float2(t1.x-t3.y, t1.y+t3.x);
    }
}

// Stockham radix-16 stage S (0,1,2) for N=4096, one j per thread.
// tw[e] = exp(-2*pi*i*e/4096), e=0..255.
template<int S>
__device__ __forceinline__ void fft_stage(const float2* __restrict__ src, float2* __restrict__ dst,
                                          const float2* __restrict__ tw, int j){
    float2 a[16];
    #pragma unroll
    for (int i=0;i<16;i++) a[i]=src[PIDX(j+(i<<8))];
    if (S>=1){
        const int L = (S==1)?16:256;
        int m = j & (L-1);
        float2 w = tw[(S==1)?(m<<4):m];       // w_{16L}^m
        float2 cw = w;
        a[1]=cmul(a[1],cw);
        #pragma unroll
        for (int i=2;i<16;i++){ cw=cmul(cw,w); a[i]=cmul(a[i],cw); }
    }
    dft16(a);
    if (S==0){
        int base = j<<4;
        #pragma unroll
        for (int r=0;r<16;r++) dst[PIDX(base+r)] = a[r];
    } else if (S==1){
        int base = (j>>4)*256 + (j&15);
        #pragma unroll
        for (int r=0;r<16;r++) dst[PIDX(base+(r<<4))] = a[r];
    } else {
        #pragma unroll
        for (int r=0;r<16;r++) dst[PIDX(j+(r<<8))] = a[r];
    }
}

// Stage 0 fused with the 2-rows-real -> 1-complex pack from global.
__device__ __forceinline__ void fft_stage0_pack(const float* __restrict__ x0,
                                                const float* __restrict__ x1,
                                                float2* __restrict__ dst, int j){
    float2 a[16];
    #pragma unroll
    for (int i=0;i<16;i++) a[i]=make_float2(x0[j+(i<<8)], x1[j+(i<<8)]);
    dft16(a);
    int base=j<<4;
    #pragma unroll
    for (int r=0;r<16;r++) dst[PIDX(base+r)]=a[r];
}

__global__ void __launch_bounds__(NT, 2)
rmix_kernel(const float* __restrict__ x,
            const float* __restrict__ Ur, const float* __restrict__ Ui,
            const float* __restrict__ Vr, const float* __restrict__ Vi,
            const float* __restrict__ Wr, const float* __restrict__ Wi,
            const float* __restrict__ P1w, const float* __restrict__ P1b,
            const float* __restrict__ P2w, const float* __restrict__ P2b,
            const float* __restrict__ alphaP,
            float* __restrict__ out)
{
    extern __shared__ float2 sm[];
    float2* A  = sm;            // 4352
    float2* E  = sm + 4352;     // 4352
    float2* tw = sm + 8704;     // 256
    float*  fscr = (float*)(sm + 8960);
    float*  dbuf = fscr;               // 4096
    float*  red  = fscr + 4096;        // 512
    float*  hidf = fscr + 4096 + 512;  // 16
    float*  pqf  = hidf + 16;          // 64

    const int tid = threadIdx.x;
    const size_t row0 = (size_t)blockIdx.x * 2;

    // twiddle table: tw[e] = exp(-2*pi*i*e/4096), e<256
    {
        float sn, cs;
        sincospif(-(float)tid * (1.0f/2048.0f), &sn, &cs);
        tw[tid] = make_float2(cs, sn);
    }
    __syncthreads();

    // ---- forward FFT of c = x0 + i*x1 ----
    fft_stage0_pack(x + row0*NS, x + (row0+1)*NS, E, tid); __syncthreads();
    fft_stage<1>(E, A, tw, tid); __syncthreads();
    fft_stage<2>(A, E, tw, tid); __syncthreads();
    // Z in E. Unpack Hermitian: X0 -> A, X1 -> E (in place, pairwise)
    for (int k = tid; k <= 2048; k += NT){
        int nk = (NS - k) & (NS-1);
        float2 Zk = E[PIDX(k)], Zn = E[PIDX(nk)];
        A[PIDX(k)]  = make_float2(0.5f*(Zk.x+Zn.x), 0.5f*(Zk.y-Zn.y));
        A[PIDX(nk)] = make_float2(0.5f*(Zn.x+Zk.x), 0.5f*(Zn.y-Zk.y));
        E[PIDX(k)]  = make_float2(0.5f*(Zk.y+Zn.y), 0.5f*(Zn.x-Zk.x));
        E[PIDX(nk)] = make_float2(0.5f*(Zn.y+Zk.y), 0.5f*(Zk.x-Zn.x));
    }
    __syncthreads();

    // ---- hidden = relu([Re z, Im z] @ P1w.T + P1b), both rows jointly ----
    float h[16];
    #pragma unroll
    for (int i = 0; i < 16; i++) h[i] = 0.0f;
    for (int k = tid; k < NS; k += NT){
        float2 a = A[PIDX(k)], b = E[PIDX(k)];
        #pragma unroll
        for (int r = 0; r < 8; r++){
            float wr_ = P1w[r*2*NS + k];
            float wi_ = P1w[r*2*NS + NS + k];
            h[r]   += a.x*wr_ + a.y*wi_;
            h[8+r] += b.x*wr_ + b.y*wi_;
        }
    }
    {
        #pragma unroll
        for (int i = 0; i < 16; i++){
            float v = h[i];
            #pragma unroll
            for (int o = 16; o > 0; o >>= 1) v += __shfl_down_sync(0xffffffffu, v, o);
            h[i] = v;
        }
        int warp = tid >> 5, lane = tid & 31;
        if (lane == 0){
            #pragma unroll
            for (int i = 0; i < 16; i++) red[warp*16 + i] = h[i];
        }
        __syncthreads();
        if (tid < 16){
            float s = 0.0f;
            #pragma unroll
            for (int w = 0; w < NT/32; w++) s += red[w*16 + tid];
            hidf[tid] = fmaxf(s + P1b[tid & 7], 0.0f);
        }
        __syncthreads();
    }

    const float alpha = *alphaP;

    // ---- per-row: delta table, then gain-scale ----
    for (int rv = 0; rv < 2; rv++){
        float2* zz = rv ? E : A;
        float hr[8];
        #pragma unroll
        for (int r = 0; r < 8; r++) hr[r] = hidf[rv*8 + r];
        for (int j = tid; j < NS; j += NT){
            const float* p2 = P2w + (size_t)j*8;
            float d = P2b[j];
            #pragma unroll
            for (int r = 0; r < 8; r++) d += hr[r]*p2[r];
            dbuf[j] = d;
        }
        __syncthreads();
        for (int k = tid; k < NS; k += NT){
            int   m2 = min(k, NS - k);
            float nf = (float)m2 * (1.0f/2048.0f);
            float t  = nf * 5.0f;
            float lb = expf(-0.5f * t * t);
            float hd = 0.5f / (1.0f + expf(-((nf - 0.6f) * 10.0f)));
            float bg = fmaxf(1.0f + lb - hd, 0.0f);
            float scaled = nf * 4095.0f;
            float fl = floorf(scaled);
            int lo = (int)fl;
            int up = (int)ceilf(scaled);
            float frac = scaled - fl;
            float dlo = dbuf[lo];
            float dhi = dbuf[up];
            float g = fmaxf(bg + alpha * (dlo + (dhi - dlo)*frac), 0.0f);
            float2 v = zz[PIDX(k)];
            zz[PIDX(k)] = make_float2(v.x*g, v.y*g);
        }
        __syncthreads();
    }

    // ---- p/q projections, both rows jointly ----
    float acc[64];
    #pragma unroll
    for (int i = 0; i < 64; i++) acc[i] = 0.0f;
    for (int k = tid; k < NS; k += NT){
        float2 a = A[PIDX(k)], b = E[PIDX(k)];
        #pragma unroll
        for (int r = 0; r < 8; r++){
            float ur = Ur[r*NS + k], ui = Ui[r*NS + k];
            float vr = Vr[r*NS + k], vi = Vi[r*NS + k];
            acc[r*2]      += a.x*ur - a.y*ui;
            acc[r*2+1]    += a.x*ui + a.y*ur;
            acc[16+r*2]   += a.x*vr - a.y*vi;
            acc[16+r*2+1] += a.x*vi + a.y*vr;
            acc[32+r*2]   += b.x*ur - b.y*ui;
            acc[32+r*2+1] += b.x*ui + b.y*ur;
            acc[48+r*2]   += b.x*vr - b.y*vi;
            acc[48+r*2+1] += b.x*vi + b.y*vr;
        }
    }
    #pragma unroll
    for (int i = 0; i < 64; i++){
        float v = acc[i];
        #pragma unroll
        for (int o = 16; o > 0; o >>= 1) v += __shfl_down_sync(0xffffffffu, v, o);
        acc[i] = v;
    }
    {
        int warp = tid >> 5, lane = tid & 31;
        if (lane == 0){
            #pragma unroll
            for (int i = 0; i < 64; i++) red[warp*64 + i] = acc[i];
        }
        __syncthreads();
        if (tid < 64){
            float s2 = 0.0f;
            #pragma unroll
            for (int w = 0; w < NT/32; w++) s2 += red[w*64 + tid];
            pqf[tid] = s2;
        }
        __syncthreads();
    }

    // ---- gamma = p*conj(q); z += gamma @ W.T ----
    float g0r[8], g0i[8], g1r[8], g1i[8];
    #pragma unroll
    for (int r = 0; r < 8; r++){
        float pr = pqf[r*2],    pi = pqf[r*2+1];
        float qr = pqf[16+r*2], qi = pqf[16+r*2+1];
        g0r[r] = pr*qr + pi*qi;
        g0i[r] = pi*qr - pr*qi;
        pr = pqf[32+r*2]; pi = pqf[32+r*2+1];
        qr = pqf[48+r*2]; qi = pqf[48+r*2+1];
        g1r[r] = pr*qr + pi*qi;
        g1i[r] = pi*qr - pr*qi;
    }
    for (int k = tid; k < NS; k += NT){
        const float* wrp = Wr + (size_t)k*8;
        const float* wip = Wi + (size_t)k*8;
        float2 v0 = A[PIDX(k)], v1 = E[PIDX(k)];
        #pragma unroll
        for (int r = 0; r < 8; r++){
            float wr_ = wrp[r], wi_ = wip[r];
            v0.x += g0r[r]*wr_ - g0i[r]*wi_;
            v0.y += g0r[r]*wi_ + g0i[r]*wr_;
            v1.x += g1r[r]*wr_ - g1i[r]*wi_;
            v1.y += g1r[r]*wi_ + g1i[r]*wr_;
        }
        A[PIDX(k)] = v0;
        E[PIDX(k)] = v1;
    }
    __syncthreads();

    // ---- combine Hermitian parts: w = h0 + i*h1 into A (pairwise, in place) ----
    for (int k = tid; k <= 2048; k += NT){
        int nk = (NS - k) & (NS-1);
        float2 a0k = A[PIDX(k)], a0n = A[PIDX(nk)];
        float2 b1k = E[PIDX(k)], b1n = E[PIDX(nk)];
        float2 wk = make_float2(0.5f*(a0k.x+a0n.x) - 0.5f*(b1k.y-b1n.y),
                                0.5f*(a0k.y-a0n.y) + 0.5f*(b1k.x+b1n.x));
        float2 wn = make_float2(0.5f*(a0n.x+a0k.x) - 0.5f*(b1n.y-b1k.y),
                                0.5f*(a0n.y-a0k.y) + 0.5f*(b1n.x+b1k.x));
        A[PIDX(k)]  = wk;
        A[PIDX(nk)] = wn;
    }
    __syncthreads();

    // ---- inverse via F = fft(w); out0 = Re F[-n]/N, out1 = Im F[-n]/N ----
    fft_stage<0>(A, E, tw, tid); __syncthreads();
    fft_stage<1>(E, A, tw, tid); __syncthreads();
    fft_stage<2>(A, E, tw, tid); __syncthreads();

    const float invn = 1.0f/4096.0f;
    for (int n = tid; n < NS; n += NT){
        int nn = (NS - n) & (NS-1);
        float2 f = E[PIDX(nn)];
        out[row0*NS + n]     = f.x * invn;
        out[(row0+1)*NS + n] = f.y * invn;
    }
}

extern "C" void kernel_launch(void* const* d_in, const int* in_sizes, int n_in,
                              void* d_out, int out_size)
{
    const float* x    = (const float*)d_in[0];
    const float* Ur   = (const float*)d_in[1];
    const float* Ui   = (const float*)d_in[2];
    const float* Vr   = (const float*)d_in[3];
    const float* Vi   = (const float*)d_in[4];
    const float* Wr   = (const float*)d_in[5];
    const float* Wi   = (const float*)d_in[6];
    const float* P1w  = (const float*)d_in[7];
    const float* P1b  = (const float*)d_in[8];
    const float* P2w  = (const float*)d_in[9];
    const float* P2b  = (const float*)d_in[10];
    const float* alph = (const float*)d_in[11];
    float* out = (float*)d_out;

    cudaFuncSetAttribute(rmix_kernel, cudaFuncAttributeMaxDynamicSharedMemorySize, SMEM_BYTES);
    rmix_kernel<<<1024, NT, SMEM_BYTES>>>(x, Ur, Ui, Vr, Vi, Wr, Wi,
                                          P1w, P1b, P2w, P2b, alph, out);
}

// round 4
// speedup vs baseline: 2.3821x; 1.1594x over previous
#include <cuda_runtime.h>
#include <math.h>

#define NT   512
#define NS   4096
#define PIDX(i) ((i) + ((i)>>4))
// float2: A0..A3 (4*4352) + tw(256) = 17664 *8 = 141312
// float:  dbuf(4*4096) + red(16*64) + hidf(32) + pqf(128) + gam(64) = 17632 *4 = 70528
#define SMEM_BYTES 211840

__device__ __forceinline__ float2 cmul(float2 a, float2 b){
    return make_float2(fmaf(a.x,b.x,-a.y*b.y), fmaf(a.x,b.y,a.y*b.x));
}
__device__ __forceinline__ float2 cadd(float2 a,float2 b){return make_float2(a.x+b.x,a.y+b.y);}
__device__ __forceinline__ float2 csub(float2 a,float2 b){return make_float2(a.x-b.x,a.y-b.y);}

__device__ __forceinline__ void dft16(float2* a){
    float2 y[16];
    #pragma unroll
    for (int b=0;b<4;b++){
        float2 x0=a[b], x1=a[4+b], x2=a[8+b], x3=a[12+b];
        float2 t0=cadd(x0,x2), t1=csub(x0,x2), t2=cadd(x1,x3), t3=csub(x1,x3);
        y[b*4+0]=cadd(t0,t2);
        y[b*4+2]=csub(t0,t2);
        y[b*4+1]=make_float2(t1.x+t3.y, t1.y-t3.x);
        y[b*4+3]=make_float2(t1.x-t3.y, t1.y+t3.x);
    }
    const float C1=0.92387953251128674f, S1=0.38268343236508978f;
    const float C2=0.70710678118654752f;
    y[5]  = cmul(y[5],  make_float2( C1,-S1));
    y[6]  = cmul(y[6],  make_float2( C2,-C2));
    y[7]  = cmul(y[7],  make_float2( S1,-C1));
    y[9]  = cmul(y[9],  make_float2( C2,-C2));
    y[10] = make_float2(y[10].y, -y[10].x);
    y[11] = cmul(y[11], make_float2(-C2,-C2));
    y[13] = cmul(y[13], make_float2( S1,-C1));
    y[14] = cmul(y[14], make_float2(-C2,-C2));
    y[15] = cmul(y[15], make_float2(-C1, S1));
    #pragma unroll
    for (int k1=0;k1<4;k1++){
        float2 x0=y[k1], x1=y[4+k1], x2=y[8+k1], x3=y[12+k1];
        float2 t0=cadd(x0,x2), t1=csub(x0,x2), t2=cadd(x1,x3), t3=csub(x1,x3);
        a[k1+0]  = cadd(t0,t2);
        a[k1+8]  = csub(t0,t2);
        a[k1+4]  = make_float2(t1.x+t3.y, t1.y-t3.x);
        a[k1+12] = make_float2(t1.x-t3.y, t1.y+t3.x);
    }
}

// Stockham radix-16 stage S (1,2) for N=4096, j in [0,256)
template<int S>
__device__ __forceinline__ void fft_stage(const float2* __restrict__ src, float2* __restrict__ dst,
                                          const float2* __restrict__ tw, int j){
    float2 a[16];
    #pragma unroll
    for (int i=0;i<16;i++) a[i]=src[PIDX(j+(i<<8))];
    {
        const int L = (S==1)?16:256;
        int m = j & (L-1);
        float2 w = tw[(S==1)?(m<<4):m];
        float2 cw = w;
        a[1]=cmul(a[1],cw);
        #pragma unroll
        for (int i=2;i<16;i++){ cw=cmul(cw,w); a[i]=cmul(a[i],cw); }
    }
    dft16(a);
    if (S==1){
        int base = (j>>4)*256 + (j&15);
        #pragma unroll
        for (int r=0;r<16;r++) dst[PIDX(base+(r<<4))] = a[r];
    } else {
        #pragma unroll
        for (int r=0;r<16;r++) dst[PIDX(j+(r<<8))] = a[r];
    }
}

__device__ __forceinline__ void fft_stage0_pack(const float* __restrict__ x0,
                                                const float* __restrict__ x1,
                                                float2* __restrict__ dst, int j){
    float2 a[16];
    #pragma unroll
    for (int i=0;i<16;i++) a[i]=make_float2(x0[j+(i<<8)], x1[j+(i<<8)]);
    dft16(a);
    int base=j<<4;
    #pragma unroll
    for (int r=0;r<16;r++) dst[PIDX(base+r)]=a[r];
}

__device__ __forceinline__ void fft_stage0_sm(const float2* __restrict__ src,
                                              float2* __restrict__ dst, int j){
    float2 a[16];
    #pragma unroll
    for (int i=0;i<16;i++) a[i]=src[PIDX(j+(i<<8))];
    dft16(a);
    int base=j<<4;
    #pragma unroll
    for (int r=0;r<16;r++) dst[PIDX(base+r)]=a[r];
}

// stage2 + direct global write: out0[n]=Re F[(NS-n)&4095]/N, out1[n]=Im .../N
__device__ __forceinline__ void fft_stage2_out(const float2* __restrict__ src,
                                               const float2* __restrict__ tw, int j,
                                               float* __restrict__ out0,
                                               float* __restrict__ out1, float invn){
    float2 a[16];
    #pragma unroll
    for (int i=0;i<16;i++) a[i]=src[PIDX(j+(i<<8))];
    {
        int m = j & 255;
        float2 w = tw[m];
        float2 cw = w;
        a[1]=cmul(a[1],cw);
        #pragma unroll
        for (int i=2;i<16;i++){ cw=cmul(cw,w); a[i]=cmul(a[i],cw); }
    }
    dft16(a);
    #pragma unroll
    for (int r=0;r<16;r++){
        int idx = j + (r<<8);
        int n = (NS - idx) & (NS-1);
        out0[n] = a[r].x * invn;
        out1[n] = a[r].y * invn;
    }
}

__global__ void __launch_bounds__(NT, 1)
rmix_kernel(const float* __restrict__ x,
            const float* __restrict__ Ur, const float* __restrict__ Ui,
            const float* __restrict__ Vr, const float* __restrict__ Vi,
            const float* __restrict__ Wr, const float* __restrict__ Wi,
            const float* __restrict__ P1w, const float* __restrict__ P1b,
            const float* __restrict__ P2w, const float* __restrict__ P2b,
            const float* __restrict__ alphaP,
            float* __restrict__ out)
{
    extern __shared__ float2 sm[];
    float2* A0 = sm;
    float2* A1 = sm + 4352;
    float2* A2 = sm + 8704;
    float2* A3 = sm + 13056;
    float2* tw = sm + 17408;          // 256
    float*  fb   = (float*)(sm + 17664);
    float*  dbuf = fb;                // 4*4096
    float*  red  = fb + 16384;        // 16*64
    float*  hidf = fb + 16384 + 1024; // 32
    float*  pqf  = hidf + 32;         // 128
    float*  gam  = pqf + 128;         // 64

    const int tid  = threadIdx.x;
    const int half = tid >> 8;        // 0/1
    const int j    = tid & 255;
    const size_t row0 = (size_t)blockIdx.x * 4;

    if (tid < 256){
        float sn, cs;
        sincospif(-(float)tid * (1.0f/2048.0f), &sn, &cs);
        tw[tid] = make_float2(cs, sn);
    }
    __syncthreads();

    // ---- forward FFT: half h packs rows (2h, 2h+1): c = x_a + i*x_b ----
    {
        const float* xa = x + (row0 + 2*half) * NS;
        const float* xb = x + (row0 + 2*half + 1) * NS;
        float2* S = half ? A2 : A0;
        float2* D = half ? A3 : A1;
        fft_stage0_pack(xa, xb, D, j); __syncthreads();
        fft_stage<1>(D, S, tw, j);     __syncthreads();
        fft_stage<2>(S, D, tw, j);     __syncthreads();
        // Z01 in A1, Z23 in A3
    }

    // ---- fused: Hermitian unpack (Z -> X0..X3) + hidden accumulation ----
    float h[32];
    #pragma unroll
    for (int i=0;i<32;i++) h[i]=0.0f;
    for (int k = tid; k <= 2048; k += NT){
        int nk = (NS - k) & (NS-1);
        float2 Zk = A1[PIDX(k)], Zn = A1[PIDX(nk)];
        float2 X0k = make_float2(0.5f*(Zk.x+Zn.x), 0.5f*(Zk.y-Zn.y));
        float2 X0n = make_float2(0.5f*(Zn.x+Zk.x), 0.5f*(Zn.y-Zk.y));
        float2 X1k = make_float2(0.5f*(Zk.y+Zn.y), 0.5f*(Zn.x-Zk.x));
        float2 X1n = make_float2(0.5f*(Zn.y+Zk.y), 0.5f*(Zk.x-Zn.x));
        float2 Yk = A3[PIDX(k)], Yn = A3[PIDX(nk)];
        float2 X2k = make_float2(0.5f*(Yk.x+Yn.x), 0.5f*(Yk.y-Yn.y));
        float2 X2n = make_float2(0.5f*(Yn.x+Yk.x), 0.5f*(Yn.y-Yk.y));
        float2 X3k = make_float2(0.5f*(Yk.y+Yn.y), 0.5f*(Yn.x-Yk.x));
        float2 X3n = make_float2(0.5f*(Yn.y+Yk.y), 0.5f*(Yk.x-Yn.x));
        A0[PIDX(k)]=X0k; A0[PIDX(nk)]=X0n;
        A1[PIDX(k)]=X1k; A1[PIDX(nk)]=X1n;
        A2[PIDX(k)]=X2k; A2[PIDX(nk)]=X2n;
        A3[PIDX(k)]=X3k; A3[PIDX(nk)]=X3n;
        bool dual = (nk != k);
        #pragma unroll
        for (int r = 0; r < 8; r++){
            float wrk = P1w[r*2*NS + k];
            float wik = P1w[r*2*NS + NS + k];
            h[r]    += X0k.x*wrk + X0k.y*wik;
            h[8+r]  += X1k.x*wrk + X1k.y*wik;
            h[16+r] += X2k.x*wrk + X2k.y*wik;
            h[24+r] += X3k.x*wrk + X3k.y*wik;
            if (dual){
                float wrn = P1w[r*2*NS + nk];
                float win = P1w[r*2*NS + NS + nk];
                h[r]    += X0n.x*wrn + X0n.y*win;
                h[8+r]  += X1n.x*wrn + X1n.y*win;
                h[16+r] += X2n.x*wrn + X2n.y*win;
                h[24+r] += X3n.x*wrn + X3n.y*win;
            }
        }
    }
    {
        #pragma unroll
        for (int i=0;i<32;i++){
            float v = h[i];
            #pragma unroll
            for (int o=16;o>0;o>>=1) v += __shfl_down_sync(0xffffffffu, v, o);
            h[i]=v;
        }
        int warp = tid >> 5, lane = tid & 31;
        if (lane == 0){
            #pragma unroll
            for (int i=0;i<32;i++) red[warp*32 + i] = h[i];
        }
        __syncthreads();
        if (tid < 32){
            float s = 0.0f;
            #pragma unroll
            for (int w=0; w<NT/32; w++) s += red[w*32 + tid];
            hidf[tid] = fmaxf(s + P1b[tid & 7], 0.0f);
        }
        __syncthreads();
    }

    const float alpha = *alphaP;

    // ---- delta tables for 4 rows (P2w read once) ----
    for (int jj = tid; jj < NS; jj += NT){
        const float* p2 = P2w + (size_t)jj*8;
        float b = P2b[jj];
        float d0=b, d1=b, d2=b, d3=b;
        #pragma unroll
        for (int r=0;r<8;r++){
            float w_ = p2[r];
            d0 += hidf[r]    * w_;
            d1 += hidf[8+r]  * w_;
            d2 += hidf[16+r] * w_;
            d3 += hidf[24+r] * w_;
        }
        dbuf[jj] = d0; dbuf[NS+jj] = d1; dbuf[2*NS+jj] = d2; dbuf[3*NS+jj] = d3;
    }
    __syncthreads();

    // ---- pass A: gain-scale all 4 rows + accumulate p (reads U once) ----
    float acc[64];
    #pragma unroll
    for (int i=0;i<64;i++) acc[i]=0.0f;
    for (int k = tid; k < NS; k += NT){
        int   m2 = min(k, NS - k);
        float nf = (float)m2 * (1.0f/2048.0f);
        float t  = nf * 5.0f;
        float lb = expf(-0.5f * t * t);
        float hd = 0.5f / (1.0f + expf(-((nf - 0.6f) * 10.0f)));
        float bg = fmaxf(1.0f + lb - hd, 0.0f);
        float scaled = nf * 4095.0f;
        float fl = floorf(scaled);
        int lo = (int)fl;
        int up = (int)ceilf(scaled);
        float frac = scaled - fl;
        float2 z[4];
        #pragma unroll
        for (int i2=0;i2<4;i2++){
            float dlo = dbuf[i2*NS + lo];
            float dhi = dbuf[i2*NS + up];
            float g = fmaxf(bg + alpha * (dlo + (dhi - dlo)*frac), 0.0f);
            float2* Zp = (i2==0)?A0:(i2==1)?A1:(i2==2)?A2:A3;
            float2 v = Zp[PIDX(k)];
            v = make_float2(v.x*g, v.y*g);
            Zp[PIDX(k)] = v;
            z[i2] = v;
        }
        #pragma unroll
        for (int r=0;r<8;r++){
            float ur = Ur[r*NS + k], ui = Ui[r*NS + k];
            #pragma unroll
            for (int i2=0;i2<4;i2++){
                acc[i2*16 + r*2]     += z[i2].x*ur - z[i2].y*ui;
                acc[i2*16 + r*2 + 1] += z[i2].x*ui + z[i2].y*ur;
            }
        }
    }
    {
        #pragma unroll
        for (int i=0;i<64;i++){
            float v = acc[i];
            #pragma unroll
            for (int o=16;o>0;o>>=1) v += __shfl_down_sync(0xffffffffu, v, o);
            acc[i]=v;
        }
        int warp = tid >> 5, lane = tid & 31;
        if (lane == 0){
            #pragma unroll
            for (int i=0;i<64;i++) red[warp*64 + i] = acc[i];
        }
        __syncthreads();
        if (tid < 64){
            float s = 0.0f;
            #pragma unroll
            for (int w=0; w<NT/32; w++) s += red[w*64 + tid];
            pqf[tid] = s;
        }
        __syncthreads();
    }

    // ---- pass B: accumulate q (reads V once; spectra already scaled) ----
    #pragma unroll
    for (int i=0;i<64;i++) acc[i]=0.0f;
    for (int k = tid; k < NS; k += NT){
        float2 z0 = A0[PIDX(k)], z1 = A1[PIDX(k)], z2 = A2[PIDX(k)], z3 = A3[PIDX(k)];
        #pragma unroll
        for (int r=0;r<8;r++){
            float vr = Vr[r*NS + k], vi = Vi[r*NS + k];
            acc[r*2]       += z0.x*vr - z0.y*vi;
            acc[r*2+1]     += z0.x*vi + z0.y*vr;
            acc[16+r*2]    += z1.x*vr - z1.y*vi;
            acc[16+r*2+1]  += z1.x*vi + z1.y*vr;
            acc[32+r*2]    += z2.x*vr - z2.y*vi;
            acc[32+r*2+1]  += z2.x*vi + z2.y*vr;
            acc[48+r*2]    += z3.x*vr - z3.y*vi;
            acc[48+r*2+1]  += z3.x*vi + z3.y*vr;
        }
    }
    {
        #pragma unroll
        for (int i=0;i<64;i++){
            float v = acc[i];
            #pragma unroll
            for (int o=16;o>0;o>>=1) v += __shfl_down_sync(0xffffffffu, v, o);
            acc[i]=v;
        }
        int warp = tid >> 5, lane = tid & 31;
        if (lane == 0){
            #pragma unroll
            for (int i=0;i<64;i++) red[warp*64 + i] = acc[i];
        }
        __syncthreads();
        if (tid < 64){
            float s = 0.0f;
            #pragma unroll
            for (int w=0; w<NT/32; w++) s += red[w*64 + tid];
            pqf[64 + tid] = s;
        }
        __syncthreads();
    }

    // ---- gamma = p * conj(q) ----
    if (tid < 32){
        int i2 = tid >> 3, r = tid & 7;
        float pr = pqf[i2*16 + r*2],      pi = pqf[i2*16 + r*2 + 1];
        float qr = pqf[64 + i2*16 + r*2], qi = pqf[64 + i2*16 + r*2 + 1];
        gam[i2*16 + r*2]     = pr*qr + pi*qi;
        gam[i2*16 + r*2 + 1] = pi*qr - pr*qi;
    }
    __syncthreads();

    // ---- fused: z += gamma @ W.T  +  Hermitian combine -> w01 (A0), w23 (A2) ----
    for (int k = tid; k <= 2048; k += NT){
        int nk = (NS - k) & (NS-1);
        bool dual = (nk != k);
        float4 wr0 = *(const float4*)(Wr + (size_t)k*8);
        float4 wr1 = *(const float4*)(Wr + (size_t)k*8 + 4);
        float4 wi0 = *(const float4*)(Wi + (size_t)k*8);
        float4 wi1 = *(const float4*)(Wi + (size_t)k*8 + 4);
        float wrk[8] = {wr0.x,wr0.y,wr0.z,wr0.w, wr1.x,wr1.y,wr1.z,wr1.w};
        float wik[8] = {wi0.x,wi0.y,wi0.z,wi0.w, wi1.x,wi1.y,wi1.z,wi1.w};
        float wrn[8], win[8];
        if (dual){
            float4 a0 = *(const float4*)(Wr + (size_t)nk*8);
            float4 a1 = *(const float4*)(Wr + (size_t)nk*8 + 4);
            float4 b0 = *(const float4*)(Wi + (size_t)nk*8);
            float4 b1 = *(const float4*)(Wi + (size_t)nk*8 + 4);
            wrn[0]=a0.x;wrn[1]=a0.y;wrn[2]=a0.z;wrn[3]=a0.w;
            wrn[4]=a1.x;wrn[5]=a1.y;wrn[6]=a1.z;wrn[7]=a1.w;
            win[0]=b0.x;win[1]=b0.y;win[2]=b0.z;win[3]=b0.w;
            win[4]=b1.x;win[5]=b1.y;win[6]=b1.z;win[7]=b1.w;
        }
        float2 vk[4], vn[4];
        #pragma unroll
        for (int i2=0;i2<4;i2++){
            float2* Zp = (i2==0)?A0:(i2==1)?A1:(i2==2)?A2:A3;
            float2 a = Zp[PIDX(k)];
            float2 b = dual ? Zp[PIDX(nk)] : a;
            #pragma unroll
            for (int r=0;r<8;r++){
                float gr = gam[i2*16 + r*2], gi = gam[i2*16 + r*2 + 1];
                a.x += gr*wrk[r] - gi*wik[r];
                a.y += gr*wik[r] + gi*wrk[r];
                if (dual){
                    b.x += gr*wrn[r] - gi*win[r];
                    b.y += gr*win[r] + gi*wrn[r];
                }
            }
            if (!dual) b = a;
            vk[i2] = a; vn[i2] = b;
        }
        // w01 = h0 + i*h1, pairwise; same for w23
        float2 wk01 = make_float2(0.5f*(vk[0].x+vn[0].x) - 0.5f*(vk[1].y-vn[1].y),
                                  0.5f*(vk[0].y-vn[0].y) + 0.5f*(vk[1].x+vn[1].x));
        float2 wn01 = make_float2(0.5f*(vn[0].x+vk[0].x) - 0.5f*(vn[1].y-vk[1].y),
                                  0.5f*(vn[0].y-vk[0].y) + 0.5f*(vn[1].x+vk[1].x));
        float2 wk23 = make_float2(0.5f*(vk[2].x+vn[2].x) - 0.5f*(vk[3].y-vn[3].y),
                                  0.5f*(vk[2].y-vn[2].y) + 0.5f*(vk[3].x+vn[3].x));
        float2 wn23 = make_float2(0.5f*(vn[2].x+vk[2].x) - 0.5f*(vn[3].y-vk[3].y),
                                  0.5f*(vn[2].y-vk[2].y) + 0.5f*(vn[3].x+vk[3].x));
        A0[PIDX(k)] = wk01; A0[PIDX(nk)] = wn01;
        A2[PIDX(k)] = wk23; A2[PIDX(nk)] = wn23;
    }
    __syncthreads();

    // ---- inverse: F = fft(w); out_a[n]=Re F[-n]/N, out_b[n]=Im F[-n]/N ----
    {
        float2* S = half ? A2 : A0;
        float2* D = half ? A3 : A1;
        fft_stage0_sm(S, D, j);      __syncthreads();
        fft_stage<1>(D, S, tw, j);   __syncthreads();
        const float invn = 1.0f/4096.0f;
        fft_stage2_out(S, tw, j,
                       out + (row0 + 2*half)*NS,
                       out + (row0 + 2*half + 1)*NS, invn);
    }
}

extern "C" void kernel_launch(void* const* d_in, const int* in_sizes, int n_in,
                              void* d_out, int out_size)
{
    const float* x    = (const float*)d_in[0];
    const float* Ur   = (const float*)d_in[1];
    const float* Ui   = (const float*)d_in[2];
    const float* Vr   = (const float*)d_in[3];
    const float* Vi   = (const float*)d_in[4];
    const float* Wr   = (const float*)d_in[5];
    const float* Wi   = (const float*)d_in[6];
    const float* P1w  = (const float*)d_in[7];
    const float* P1b  = (const float*)d_in[8];
    const float* P2w  = (const float*)d_in[9];
    const float* P2b  = (const float*)d_in[10];
    const float* alph = (const float*)d_in[11];
    float* out = (float*)d_out;

    cudaFuncSetAttribute(rmix_kernel, cudaFuncAttributeMaxDynamicSharedMemorySize, SMEM_BYTES);
    rmix_kernel<<<512, NT, SMEM_BYTES>>>(x, Ur, Ui, Vr, Vi, Wr, Wi,
                                         P1w, P1b, P2w, P2b, alph, out);
}

// round 6
// speedup vs baseline: 2.9691x; 1.2464x over previous
#include <cuda_runtime.h>
#include <math.h>

#define NT   256
#define NS   4096
#define PIDX(i) ((i) + ((i)>>4))
// float2: A(4352)+E(4352)+tw(256)=8960*8=71680 ; floats: dbuf(8192)+red(512)+hidf(16)+pqf(64)+gam(32)=8816*4=35264
#define SMEM_BYTES 106944

__device__ __forceinline__ float2 cmul(float2 a, float2 b){
    return make_float2(fmaf(a.x,b.x,-a.y*b.y), fmaf(a.x,b.y,a.y*b.x));
}
__device__ __forceinline__ float2 cadd(float2 a,float2 b){return make_float2(a.x+b.x,a.y+b.y);}
__device__ __forceinline__ float2 csub(float2 a,float2 b){return make_float2(a.x-b.x,a.y-b.y);}

__device__ __forceinline__ void dft16(float2* a){
    float2 y[16];
    #pragma unroll
    for (int b=0;b<4;b++){
        float2 x0=a[b], x1=a[4+b], x2=a[8+b], x3=a[12+b];
        float2 t0=cadd(x0,x2), t1=csub(x0,x2), t2=cadd(x1,x3), t3=csub(x1,x3);
        y[b*4+0]=cadd(t0,t2);
        y[b*4+2]=csub(t0,t2);
        y[b*4+1]=make_float2(t1.x+t3.y, t1.y-t3.x);
        y[b*4+3]=make_float2(t1.x-t3.y, t1.y+t3.x);
    }
    const float C1=0.92387953251128674f, S1=0.38268343236508978f;
    const float C2=0.70710678118654752f;
    y[5]  = cmul(y[5],  make_float2( C1,-S1));
    y[6]  = cmul(y[6],  make_float2( C2,-C2));
    y[7]  = cmul(y[7],  make_float2( S1,-C1));
    y[9]  = cmul(y[9],  make_float2( C2,-C2));
    y[10] = make_float2(y[10].y, -y[10].x);
    y[11] = cmul(y[11], make_float2(-C2,-C2));
    y[13] = cmul(y[13], make_float2( S1,-C1));
    y[14] = cmul(y[14], make_float2(-C2,-C2));
    y[15] = cmul(y[15], make_float2(-C1, S1));
    #pragma unroll
    for (int k1=0;k1<4;k1++){
        float2 x0=y[k1], x1=y[4+k1], x2=y[8+k1], x3=y[12+k1];
        float2 t0=cadd(x0,x2), t1=csub(x0,x2), t2=cadd(x1,x3), t3=csub(x1,x3);
        a[k1+0]  = cadd(t0,t2);
        a[k1+8]  = csub(t0,t2);
        a[k1+4]  = make_float2(t1.x+t3.y, t1.y-t3.x);
        a[k1+12] = make_float2(t1.x-t3.y, t1.y+t3.x);
    }
}

template<int S>
__device__ __forceinline__ void fft_stage(const float2* __restrict__ src, float2* __restrict__ dst,
                                          const float2* __restrict__ tw, int j){
    float2 a[16];
    #pragma unroll
    for (int i=0;i<16;i++) a[i]=src[PIDX(j+(i<<8))];
    {
        const int L = (S==1)?16:256;
        int m = j & (L-1);
        float2 w = tw[(S==1)?(m<<4):m];
        float2 cw = w;
        a[1]=cmul(a[1],cw);
        #pragma unroll
        for (int i=2;i<16;i++){ cw=cmul(cw,w); a[i]=cmul(a[i],cw); }
    }
    dft16(a);
    if (S==1){
        int base = (j>>4)*256 + (j&15);
        #pragma unroll
        for (int r=0;r<16;r++) dst[PIDX(base+(r<<4))] = a[r];
    } else {
        #pragma unroll
        for (int r=0;r<16;r++) dst[PIDX(j+(r<<8))] = a[r];
    }
}

__device__ __forceinline__ void fft_stage0_pack(const float* __restrict__ x0,
                                                const float* __restrict__ x1,
                                                float2* __restrict__ dst, int j){
    float2 a[16];
    #pragma unroll
    for (int i=0;i<16;i++) a[i]=make_float2(x0[j+(i<<8)], x1[j+(i<<8)]);
    dft16(a);
    int base=j<<4;
    #pragma unroll
    for (int r=0;r<16;r++) dst[PIDX(base+r)]=a[r];
}

__device__ __forceinline__ void fft_stage0_sm(const float2* __restrict__ src,
                                              float2* __restrict__ dst, int j){
    float2 a[16];
    #pragma unroll
    for (int i=0;i<16;i++) a[i]=src[PIDX(j+(i<<8))];
    dft16(a);
    int base=j<<4;
    #pragma unroll
    for (int r=0;r<16;r++) dst[PIDX(base+r)]=a[r];
}

__device__ __forceinline__ void fft_stage2_out(const float2* __restrict__ src,
                                               const float2* __restrict__ tw, int j,
                                               float* __restrict__ out0,
                                               float* __restrict__ out1, float invn){
    float2 a[16];
    #pragma unroll
    for (int i=0;i<16;i++) a[i]=src[PIDX(j+(i<<8))];
    {
        int m = j & 255;
        float2 w = tw[m];
        float2 cw = w;
        a[1]=cmul(a[1],cw);
        #pragma unroll
        for (int i=2;i<16;i++){ cw=cmul(cw,w); a[i]=cmul(a[i],cw); }
    }
    dft16(a);
    #pragma unroll
    for (int r=0;r<16;r++){
        int idx = j + (r<<8);
        int n = (NS - idx) & (NS-1);
        out0[n] = a[r].x * invn;
        out1[n] = a[r].y * invn;
    }
}

__global__ void __launch_bounds__(NT, 2)
rmix_kernel(const float* __restrict__ x,
            const float* __restrict__ Ur, const float* __restrict__ Ui,
            const float* __restrict__ Vr, const float* __restrict__ Vi,
            const float* __restrict__ Wr, const float* __restrict__ Wi,
            const float* __restrict__ P1w, const float* __restrict__ P1b,
            const float* __restrict__ P2w, const float* __restrict__ P2b,
            const float* __restrict__ alphaP,
            float* __restrict__ out)
{
    extern __shared__ float2 sm[];
    float2* A  = sm;                  // 4352 : row0 spectrum / scratch
    float2* E  = sm + 4352;           // 4352 : row1 spectrum / scratch
    float2* tw = sm + 8704;           // 256
    float*  fb   = (float*)(sm + 8960);
    float*  dbuf = fb;                // 2*4096
    float*  red  = fb + 8192;         // 512
    float*  hidf = fb + 8192 + 512;   // 16
    float*  pqf  = hidf + 16;         // 64
    float*  gam  = pqf + 64;          // 32

    const int tid = threadIdx.x;
    const size_t row0 = (size_t)blockIdx.x * 2;

    {
        float sn, cs;
        sincospif(-(float)tid * (1.0f/2048.0f), &sn, &cs);
        tw[tid] = make_float2(cs, sn);
    }
    __syncthreads();

    // ---- forward FFT of c = x0 + i*x1 ----
    fft_stage0_pack(x + row0*NS, x + (row0+1)*NS, E, tid); __syncthreads();
    fft_stage<1>(E, A, tw, tid); __syncthreads();
    fft_stage<2>(A, E, tw, tid); __syncthreads();   // Z in E

    // ---- fused: Hermitian unpack (Z -> X0 in A, X1 in E) + hidden accumulation ----
    float h[16];
    #pragma unroll
    for (int i=0;i<16;i++) h[i]=0.0f;
    for (int k = tid; k <= 2048; k += NT){
        int nk = (NS - k) & (NS-1);
        float2 Zk = E[PIDX(k)], Zn = E[PIDX(nk)];
        float2 X0k = make_float2(0.5f*(Zk.x+Zn.x), 0.5f*(Zk.y-Zn.y));
        float2 X0n = make_float2(0.5f*(Zn.x+Zk.x), 0.5f*(Zn.y-Zk.y));
        float2 X1k = make_float2(0.5f*(Zk.y+Zn.y), 0.5f*(Zn.x-Zk.x));
        float2 X1n = make_float2(0.5f*(Zn.y+Zk.y), 0.5f*(Zk.x-Zn.x));
        A[PIDX(k)]=X0k; A[PIDX(nk)]=X0n;
        E[PIDX(k)]=X1k; E[PIDX(nk)]=X1n;
        bool dual = (nk != k);
        #pragma unroll
        for (int r = 0; r < 8; r++){
            float wrk = P1w[r*2*NS + k];
            float wik = P1w[r*2*NS + NS + k];
            h[r]   += X0k.x*wrk + X0k.y*wik;
            h[8+r] += X1k.x*wrk + X1k.y*wik;
            if (dual){
                float wrn = P1w[r*2*NS + nk];
                float win = P1w[r*2*NS + NS + nk];
                h[r]   += X0n.x*wrn + X0n.y*win;
                h[8+r] += X1n.x*wrn + X1n.y*win;
            }
        }
    }
    {
        #pragma unroll
        for (int i=0;i<16;i++){
            float v = h[i];
            #pragma unroll
            for (int o=16;o>0;o>>=1) v += __shfl_down_sync(0xffffffffu, v, o);
            h[i]=v;
        }
        int warp = tid >> 5, lane = tid & 31;
        if (lane == 0){
            #pragma unroll
            for (int i=0;i<16;i++) red[warp*16 + i] = h[i];
        }
        __syncthreads();
        if (tid < 16){
            float s = 0.0f;
            #pragma unroll
            for (int w=0; w<NT/32; w++) s += red[w*16 + tid];
            hidf[tid] = fmaxf(s + P1b[tid & 7], 0.0f);
        }
        __syncthreads();
    }

    const float alpha = *alphaP;

    // ---- delta tables for 2 rows (P2w read once) ----
    for (int jj = tid; jj < NS; jj += NT){
        const float* p2 = P2w + (size_t)jj*8;
        float b = P2b[jj];
        float d0=b, d1=b;
        #pragma unroll
        for (int r=0;r<8;r++){
            float w_ = p2[r];
            d0 += hidf[r]   * w_;
            d1 += hidf[8+r] * w_;
        }
        dbuf[jj] = d0; dbuf[NS+jj] = d1;
    }
    __syncthreads();

    // ---- fused: gain-scale + joint p/q accumulation (U,V read once) ----
    float acc[64];
    #pragma unroll
    for (int i=0;i<64;i++) acc[i]=0.0f;
    for (int k = tid; k < NS; k += NT){
        int   m2 = min(k, NS - k);
        float nf = (float)m2 * (1.0f/2048.0f);
        float t  = nf * 5.0f;
        float lb = expf(-0.5f * t * t);
        float hd = 0.5f / (1.0f + expf(-((nf - 0.6f) * 10.0f)));
        float bg = fmaxf(1.0f + lb - hd, 0.0f);
        float scaled = nf * 4095.0f;
        float fl = floorf(scaled);
        int lo = (int)fl;
        int up = (int)ceilf(scaled);
        float frac = scaled - fl;
        float dlo0 = dbuf[lo],    dhi0 = dbuf[up];
        float dlo1 = dbuf[NS+lo], dhi1 = dbuf[NS+up];
        float g0 = fmaxf(bg + alpha * (dlo0 + (dhi0 - dlo0)*frac), 0.0f);
        float g1 = fmaxf(bg + alpha * (dlo1 + (dhi1 - dlo1)*frac), 0.0f);
        float2 z0 = A[PIDX(k)]; z0 = make_float2(z0.x*g0, z0.y*g0); A[PIDX(k)] = z0;
        float2 z1 = E[PIDX(k)]; z1 = make_float2(z1.x*g1, z1.y*g1); E[PIDX(k)] = z1;
        #pragma unroll
        for (int r=0;r<8;r++){
            float ur = Ur[r*NS + k], ui = Ui[r*NS + k];
            float vr = Vr[r*NS + k], vi = Vi[r*NS + k];
            acc[r*2]      += z0.x*ur - z0.y*ui;   // p row0
            acc[r*2+1]    += z0.x*ui + z0.y*ur;
            acc[16+r*2]   += z0.x*vr - z0.y*vi;   // q row0
            acc[16+r*2+1] += z0.x*vi + z0.y*vr;
            acc[32+r*2]   += z1.x*ur - z1.y*ui;   // p row1
            acc[32+r*2+1] += z1.x*ui + z1.y*ur;
            acc[48+r*2]   += z1.x*vr - z1.y*vi;   // q row1
            acc[48+r*2+1] += z1.x*vi + z1.y*vr;
        }
    }
    {
        #pragma unroll
        for (int i=0;i<64;i++){
            float v = acc[i];
            #pragma unroll
            for (int o=16;o>0;o>>=1) v += __shfl_down_sync(0xffffffffu, v, o);
            acc[i]=v;
        }
        int warp = tid >> 5, lane = tid & 31;
        if (lane == 0){
            #pragma unroll
            for (int i=0;i<64;i++) red[warp*64 + i] = acc[i];
        }
        __syncthreads();
        if (tid < 64){
            float s = 0.0f;
            #pragma unroll
            for (int w=0; w<NT/32; w++) s += red[w*64 + tid];
            pqf[tid] = s;
        }
        __syncthreads();
    }

    // ---- gamma = p * conj(q) : layout pqf[row*32 + {p:0..15, q:16..31}] ----
    if (tid < 16){
        int row = tid >> 3, r = tid & 7;
        float pr = pqf[row*32 + r*2],      pi = pqf[row*32 + r*2 + 1];
        float qr = pqf[row*32 + 16 + r*2], qi = pqf[row*32 + 16 + r*2 + 1];
        gam[row*16 + r*2]     = pr*qr + pi*qi;
        gam[row*16 + r*2 + 1] = pi*qr - pr*qi;
    }
    __syncthreads();

    // ---- fused: z += gamma @ W.T  +  Hermitian combine -> w in A ----
    for (int k = tid; k <= 2048; k += NT){
        int nk = (NS - k) & (NS-1);
        bool dual = (nk != k);
        float4 wr0 = *(const float4*)(Wr + (size_t)k*8);
        float4 wr1 = *(const float4*)(Wr + (size_t)k*8 + 4);
        float4 wi0 = *(const float4*)(Wi + (size_t)k*8);
        float4 wi1 = *(const float4*)(Wi + (size_t)k*8 + 4);
        float wrk[8] = {wr0.x,wr0.y,wr0.z,wr0.w, wr1.x,wr1.y,wr1.z,wr1.w};
        float wik[8] = {wi0.x,wi0.y,wi0.z,wi0.w, wi1.x,wi1.y,wi1.z,wi1.w};
        float wrn[8], win[8];
        if (dual){
            float4 a0 = *(const float4*)(Wr + (size_t)nk*8);
            float4 a1 = *(const float4*)(Wr + (size_t)nk*8 + 4);
            float4 b0 = *(const float4*)(Wi + (size_t)nk*8);
            float4 b1 = *(const float4*)(Wi + (size_t)nk*8 + 4);
            wrn[0]=a0.x;wrn[1]=a0.y;wrn[2]=a0.z;wrn[3]=a0.w;
            wrn[4]=a1.x;wrn[5]=a1.y;wrn[6]=a1.z;wrn[7]=a1.w;
            win[0]=b0.x;win[1]=b0.y;win[2]=b0.z;win[3]=b0.w;
            win[4]=b1.x;win[5]=b1.y;win[6]=b1.z;win[7]=b1.w;
        }
        float2 v0k = A[PIDX(k)], v0n = dual ? A[PIDX(nk)] : v0k;
        float2 v1k = E[PIDX(k)], v1n = dual ? E[PIDX(nk)] : v1k;
        #pragma unroll
        for (int r=0;r<8;r++){
            float g0r_ = gam[r*2],      g0i_ = gam[r*2+1];
            float g1r_ = gam[16+r*2],   g1i_ = gam[16+r*2+1];
            v0k.x += g0r_*wrk[r] - g0i_*wik[r];
            v0k.y += g0r_*wik[r] + g0i_*wrk[r];
            v1k.x += g1r_*wrk[r] - g1i_*wik[r];
            v1k.y += g1r_*wik[r] + g1i_*wrk[r];
            if (dual){
                v0n.x += g0r_*wrn[r] - g0i_*win[r];
                v0n.y += g0r_*win[r] + g0i_*wrn[r];
                v1n.x += g1r_*wrn[r] - g1i_*win[r];
                v1n.y += g1r_*win[r] + g1i_*wrn[r];
            }
        }
        if (!dual){ v0n = v0k; v1n = v1k; }
        // w = h0 + i*h1, pairwise
        float2 wk = make_float2(0.5f*(v0k.x+v0n.x) - 0.5f*(v1k.y-v1n.y),
                                0.5f*(v0k.y-v0n.y) + 0.5f*(v1k.x+v1n.x));
        float2 wn = make_float2(0.5f*(v0n.x+v0k.x) - 0.5f*(v1n.y-v1k.y),
                                0.5f*(v0n.y-v0k.y) + 0.5f*(v1n.x+v1k.x));
        A[PIDX(k)] = wk; A[PIDX(nk)] = wn;
    }
    __syncthreads();

    // ---- inverse: F = fft(w); out0[n]=Re F[-n]/N, out1[n]=Im F[-n]/N ----
    fft_stage0_sm(A, E, tid);    __syncthreads();
    fft_stage<1>(E, A, tw, tid); __syncthreads();
    const float invn = 1.0f/4096.0f;
    fft_stage2_out(A, tw, tid, out + row0*NS, out + (row0+1)*NS, invn);
}

extern "C" void kernel_launch(void* const* d_in, const int* in_sizes, int n_in,
                              void* d_out, int out_size)
{
    const float* x    = (const float*)d_in[0];
    const float* Ur   = (const float*)d_in[1];
    const float* Ui   = (const float*)d_in[2];
    const float* Vr   = (const float*)d_in[3];
    const float* Vi   = (const float*)d_in[4];
    const float* Wr   = (const float*)d_in[5];
    const float* Wi   = (const float*)d_in[6];
    const float* P1w  = (const float*)d_in[7];
    const float* P1b  = (const float*)d_in[8];
    const float* P2w  = (const float*)d_in[9];
    const float* P2b  = (const float*)d_in[10];
    const float* alph = (const float*)d_in[11];
    float* out = (float*)d_out;

    cudaFuncSetAttribute(rmix_kernel, cudaFuncAttributeMaxDynamicSharedMemorySize, SMEM_BYTES);
    rmix_kernel<<<1024, NT, SMEM_BYTES>>>(x, Ur, Ui, Vr, Vi, Wr, Wi,
                                          P1w, P1b, P2w, P2b, alph, out);
}